// round 8
// baseline (speedup 1.0000x reference)
#include <cuda_runtime.h>
#include <cuda_bf16.h>
#include <stdint.h>

// 12-qubit StronglyEntanglingLayers simulator (QDEPTH=8, WIRES=12, reps=1).
//  - normalize/denormalize cancels (circuit is linear) -> skipped
//  - CNOT layers = GF(2)-linear bit maps, host-precomputed, folded into addressing
//  - TWO batch states per CTA, SoA-packed in 64-bit regs -> all gate math uses
//    packed fma.rn.f32x2 (FFMA2): half the FMA instructions per state
//  - conflict-free LDS.128: host picks coset bases with lane bits 0-2 -> addr
//    bits 0-2 invertible (8-lane phase) and lane bits 0-3 -> addr bits 0-3
//  - output: out_size == B*4096 -> real-part float32; == 2*B*4096 -> interleaved.

#define NWIRES 12
#define QD 8
#define NSTATE 4096
#define SMASK (NSTATE - 1)
#define TPB 256

struct GParams {
    unsigned short C[QD][3][8];   // coset basis: low 12 bits = vector, bits 12..15 = flip gen
    unsigned short Mm[QD][3][4];  // gate masks (physical images of group logical bits)
    unsigned short Mf[NWIRES];    // final accumulated map (output addressing)
};

typedef unsigned long long ull;

__device__ __forceinline__ ull pk2(float lo, float hi) {
    ull r; asm("mov.b64 %0, {%1, %2};" : "=l"(r) : "f"(lo), "f"(hi)); return r;
}
__device__ __forceinline__ void upk2(ull v, float& lo, float& hi) {
    asm("mov.b64 {%0, %1}, %2;" : "=f"(lo), "=f"(hi) : "l"(v));
}
__device__ __forceinline__ ull fma2(ull a, ull b, ull c) {
    ull d; asm("fma.rn.f32x2 %0, %1, %2, %3;" : "=l"(d) : "l"(a), "l"(b), "l"(c)); return d;
}
__device__ __forceinline__ ull mul2(ull a, ull b) {
    ull d; asm("mul.rn.f32x2 %0, %1, %2;" : "=l"(d) : "l"(a), "l"(b)); return d;
}

__global__ __launch_bounds__(TPB) void qsim_kernel(
    const float* __restrict__ x, long long xN,
    const float* __restrict__ wts, int wN,
    float* __restrict__ outraw, long long outFloats, int outMode,
    int batch, GParams gp)
{
    extern __shared__ float4 st4[];        // 4096 x (s0re, s0im, s1re, s1im) = 64 KB
    __shared__ float sU[QD * NWIRES][8];   // 3 KB rot matrices

    const int t = threadIdx.x;
    const int s0 = 2 * blockIdx.x;
    const int s1 = s0 + 1;

    // ---- Rot matrices (one gate per thread, 96 gates) ----
    if (t < QD * NWIRES && t * 3 + 2 < wN) {
        float phi = tanhf(wts[t * 3 + 0]);
        float th  = tanhf(wts[t * 3 + 1]);
        float om  = tanhf(wts[t * 3 + 2]);
        float si, co;  sincosf(0.5f * th, &si, &co);
        float a  = 0.5f * (phi + om);
        float bq = 0.5f * (phi - om);
        float sa, ca;  sincosf(a,  &sa, &ca);
        float sb, cb;  sincosf(bq, &sb, &cb);
        sU[t][0] =  ca * co;  sU[t][1] = -sa * co;   // U00
        sU[t][2] = -cb * si;  sU[t][3] = -sb * si;   // U01
        sU[t][4] =  cb * si;  sU[t][5] = -sb * si;   // U10
        sU[t][6] =  ca * co;  sU[t][7] =  sa * co;   // U11
    }

    // ---- load both states (imag = 0); normalization skipped (linear circuit) ----
    {
        const long long b0 = (long long)s0 * NSTATE;
        const long long b1 = (long long)s1 * NSTATE;
        const bool has1 = (s1 < batch);
        #pragma unroll
        for (int j = 0; j < 16; j++) {
            int i = j * TPB + t;
            float r0 = (b0 + i < xN) ? x[b0 + i] : 0.0f;
            float r1 = (has1 && b1 + i < xN) ? x[b1 + i] : 0.0f;
            st4[i] = make_float4(r0, 0.0f, r1, 0.0f);
        }
    }
    __syncthreads();

    #pragma unroll 1
    for (int l = 0; l < QD; l++) {
        #pragma unroll
        for (int g = 0; g < 3; g++) {
            // thread -> coset representative (conflict-free by construction) + flip bits
            unsigned acc = 0;
            #pragma unroll
            for (int k = 0; k < 8; k++)
                acc ^= (0u - (((unsigned)t >> k) & 1u)) & (unsigned)gp.C[l][g][k];
            const unsigned pb   = acc & 0xFFFu;
            const unsigned flip = acc >> 12;

            const unsigned m0 = gp.Mm[l][g][0], m1 = gp.Mm[l][g][1];
            const unsigned m2 = gp.Mm[l][g][2], m3 = gp.Mm[l][g][3];

            ull cre[16], cim[16];
            #pragma unroll
            for (int j = 0; j < 16; j++) {
                unsigned a2 = (pb ^ ((j & 1) ? m0 : 0u) ^ ((j & 2) ? m1 : 0u)
                                  ^ ((j & 4) ? m2 : 0u) ^ ((j & 8) ? m3 : 0u)) & SMASK;
                float4 v = st4[a2];
                cre[j] = pk2(v.x, v.z);
                cim[j] = pk2(v.y, v.w);
            }

            // ---- 4 Rot gates in packed registers: slot sl -> wire 4g+3-sl ----
            #pragma unroll
            for (int sl = 0; sl < 4; sl++) {
                const int wire = 4 * g + 3 - sl;
                const float* U = sU[l * NWIRES + wire];
                float u00r = U[0], u00i = U[1], u01r = U[2], u01i = U[3];
                float u10r = U[4], u10i = U[5], u11r = U[6], u11i = U[7];
                if (flip & (1u << sl)) {
                    float tr;
                    tr = u00r; u00r = u11r; u11r = tr;
                    tr = u00i; u00i = u11i; u11i = tr;
                    tr = u01r; u01r = u10r; u10r = tr;
                    tr = u01i; u01i = u10i; u10i = tr;
                }
                // packed coefficient broadcasts
                const ull p00r = pk2(u00r, u00r), p00i = pk2(u00i, u00i);
                const ull n00i = pk2(-u00i, -u00i);
                const ull p01r = pk2(u01r, u01r), p01i = pk2(u01i, u01i);
                const ull n01i = pk2(-u01i, -u01i);
                const ull p10r = pk2(u10r, u10r), p10i = pk2(u10i, u10i);
                const ull n10i = pk2(-u10i, -u10i);
                const ull p11r = pk2(u11r, u11r), p11i = pk2(u11i, u11i);
                const ull n11i = pk2(-u11i, -u11i);

                #pragma unroll
                for (int j = 0; j < 16; j++) {
                    if (j & (1 << sl)) continue;
                    const int j1 = j | (1 << sl);
                    ull are = cre[j],  aim = cim[j];
                    ull bre = cre[j1], bim = cim[j1];
                    ull o0r = mul2(p00r, are);
                    o0r = fma2(n00i, aim, o0r);
                    o0r = fma2(p01r, bre, o0r);
                    o0r = fma2(n01i, bim, o0r);
                    ull o0i = mul2(p00r, aim);
                    o0i = fma2(p00i, are, o0i);
                    o0i = fma2(p01r, bim, o0i);
                    o0i = fma2(p01i, bre, o0i);
                    ull o1r = mul2(p10r, are);
                    o1r = fma2(n10i, aim, o1r);
                    o1r = fma2(p11r, bre, o1r);
                    o1r = fma2(n11i, bim, o1r);
                    ull o1i = mul2(p10r, aim);
                    o1i = fma2(p10i, are, o1i);
                    o1i = fma2(p11r, bim, o1i);
                    o1i = fma2(p11i, bre, o1i);
                    cre[j]  = o0r;  cim[j]  = o0i;
                    cre[j1] = o1r;  cim[j1] = o1i;
                }
            }

            #pragma unroll
            for (int j = 0; j < 16; j++) {
                unsigned a2 = (pb ^ ((j & 1) ? m0 : 0u) ^ ((j & 2) ? m1 : 0u)
                                  ^ ((j & 4) ? m2 : 0u) ^ ((j & 8) ? m3 : 0u)) & SMASK;
                float4 w;
                upk2(cre[j], w.x, w.z);
                upk2(cim[j], w.y, w.w);
                st4[a2] = w;
            }
            __syncthreads();
        }
    }

    // ---- output: logical index j*256+t lives at physical Mf(index) ----
    unsigned mf[NWIRES];
    #pragma unroll
    for (int b = 0; b < NWIRES; b++) mf[b] = gp.Mf[b];

    unsigned Mt = 0;
    #pragma unroll
    for (int k = 0; k < 8; k++)
        Mt ^= (0u - (((unsigned)t >> k) & 1u)) & mf[k];

    const long long b0 = (long long)s0 * NSTATE;
    const long long b1 = (long long)s1 * NSTATE;
    const bool has1 = (s1 < batch);
    #pragma unroll
    for (int j = 0; j < 16; j++) {
        unsigned a2 = (Mt ^ ((j & 1) ? mf[8]  : 0u) ^ ((j & 2) ? mf[9]  : 0u)
                          ^ ((j & 4) ? mf[10] : 0u) ^ ((j & 8) ? mf[11] : 0u)) & SMASK;
        const int i = j * TPB + t;
        float4 v = st4[a2];
        if (outMode == 0) {
            if (b0 + i < outFloats) outraw[b0 + i] = v.x;
            if (has1 && b1 + i < outFloats) outraw[b1 + i] = v.z;
        } else {
            long long f0 = 2 * (b0 + i);
            if (f0 + 1 < outFloats) { outraw[f0] = v.x; outraw[f0 + 1] = v.y; }
            if (has1) {
                long long f1 = 2 * (b1 + i);
                if (f1 + 1 < outFloats) { outraw[f1] = v.z; outraw[f1 + 1] = v.w; }
            }
        }
    }
}

// ---------------- host ----------------

static inline unsigned short xor_map(const unsigned short* cols, unsigned v) {
    unsigned acc = 0;
    for (int k = 0; k < NWIRES; k++)
        if ((v >> k) & 1u) acc ^= cols[k];
    return (unsigned short)acc;
}

extern "C" void kernel_launch(void* const* d_in, const int* in_sizes, int n_in,
                              void* d_out, int out_size)
{
    const float* x   = nullptr;
    const float* wts = nullptr;
    long long xN = 0; int wN = 0, batch = 0;
    for (int i = 0; i < n_in; i++) {
        const int sz = in_sizes[i];
        if (sz == QD * NWIRES * 3) {
            wts = (const float*)d_in[i];  wN = sz;
        } else if (sz >= NSTATE && (sz % NSTATE) == 0) {
            x = (const float*)d_in[i];  xN = sz;  batch = sz / NSTATE;
        }
    }
    if (!x || !wts || batch <= 0) return;

    const long long nAmp = (long long)batch * NSTATE;
    int outMode = (out_size == 2LL * nAmp) ? 1 : 0;
    long long outFloats = (long long)out_size;

    // ---- accumulated GF(2) maps per layer ----
    unsigned short Ml[QD + 1][NWIRES];
    {
        unsigned short M[NWIRES];
        for (int b = 0; b < NWIRES; b++) M[b] = (unsigned short)(1u << b);
        for (int l = 0; l < QD; l++) {
            for (int b = 0; b < NWIRES; b++) Ml[l][b] = M[b];
            const int r = (l % (NWIRES - 1)) + 1;
            unsigned short Mn[NWIRES];
            for (int b = 0; b < NWIRES; b++) {
                unsigned i = 1u << b;
                for (int w = NWIRES - 1; w >= 0; w--) {
                    const int bc = NWIRES - 1 - w;
                    const int bt = NWIRES - 1 - ((w + r) % NWIRES);
                    i ^= ((i >> bc) & 1u) << bt;
                }
                Mn[b] = xor_map(M, i);
            }
            for (int b = 0; b < NWIRES; b++) M[b] = Mn[b];
        }
        for (int b = 0; b < NWIRES; b++) Ml[QD][b] = M[b];
    }

    GParams gp;
    for (int b = 0; b < NWIRES; b++) gp.Mf[b] = Ml[QD][b];

    for (int l = 0; l < QD; l++) {
        // inverse of M_l via [A|I] row reduction
        unsigned rows[NWIRES];
        for (int i = 0; i < NWIRES; i++) {
            unsigned rr = 0;
            for (int j = 0; j < NWIRES; j++)
                rr |= ((Ml[l][j] >> i) & 1u) << j;
            rows[i] = rr | (1u << (12 + i));
        }
        for (int col = 0; col < NWIRES; col++) {
            int piv = -1;
            for (int i = col; i < NWIRES; i++)
                if ((rows[i] >> col) & 1u) { piv = i; break; }
            unsigned tmp = rows[col]; rows[col] = rows[piv]; rows[piv] = tmp;
            for (int i = 0; i < NWIRES; i++)
                if (i != col && ((rows[i] >> col) & 1u)) rows[i] ^= rows[col];
        }
        unsigned short Minv[NWIRES];
        for (int b = 0; b < NWIRES; b++) {
            unsigned v = 0;
            for (int i = 0; i < NWIRES; i++)
                v |= ((rows[i] >> (12 + b)) & 1u) << i;
            Minv[b] = (unsigned short)v;
        }

        for (int g = 0; g < 3; g++) {
            const int lb = 8 - 4 * g;
            unsigned short m4[4];
            for (int sl = 0; sl < 4; sl++) {
                m4[sl] = Ml[l][lb + sl];
                gp.Mm[l][g][sl] = m4[sl];
            }

            unsigned led[NWIRES]; for (int i = 0; i < NWIRES; i++) led[i] = 0;
            auto tryAdd12 = [&](unsigned v, unsigned* L) -> bool {
                while (v) {
                    int b = 31 - __builtin_clz(v);
                    if (!L[b]) { L[b] = v; return true; }
                    v ^= L[b];
                }
                return false;
            };
            for (int sl = 0; sl < 4; sl++) tryAdd12(m4[sl], led);

            unsigned led4[4] = {0, 0, 0, 0};   // low-4 echelon (lanes 0-15 distinct)
            unsigned led3[3] = {0, 0, 0};      // low-3 echelon (8-lane LDS.128 phases)
            auto tryAddN = [&](unsigned v, unsigned* L, unsigned maskN) -> bool {
                v &= maskN;
                while (v) {
                    int b = 31 - __builtin_clz(v);
                    if (!L[b]) { L[b] = v; return true; }
                    v ^= L[b];
                }
                return false;
            };

            int dlist[8], nd = 0;
            for (int b = 0; b < NWIRES; b++)
                if (b < lb || b > lb + 3) dlist[nd++] = b;

            for (int k = 0; k < 8; k++) {
                unsigned chosen = 0; int found = 0;
                for (int pass = 0; pass < 2 && !found; pass++) {
                    const int lim = (pass == 0) ? 256 : 4096;
                    for (int u = 1; u < lim && !found; u++) {
                        unsigned cand;
                        if (pass == 0) {
                            cand = 0;
                            for (int i = 0; i < 8; i++)
                                if ((u >> i) & 1) cand ^= Ml[l][dlist[i]];
                        } else {
                            cand = (unsigned)u;
                        }
                        unsigned L12[NWIRES]; for (int i = 0; i < NWIRES; i++) L12[i] = led[i];
                        if (!tryAdd12(cand, L12)) continue;
                        if (k < 4) {
                            unsigned L4[4] = {led4[0], led4[1], led4[2], led4[3]};
                            if (!tryAddN(cand, L4, 15u)) continue;
                            if (k < 3) {
                                unsigned L3[3] = {led3[0], led3[1], led3[2]};
                                if (!tryAddN(cand, L3, 7u)) continue;
                                for (int i = 0; i < 3; i++) led3[i] = L3[i];
                            }
                            for (int i = 0; i < 4; i++) led4[i] = L4[i];
                        }
                        for (int i = 0; i < NWIRES; i++) led[i] = L12[i];
                        chosen = cand; found = 1;
                    }
                }
                unsigned vlog = 0;
                for (int i = 0; i < NWIRES; i++)
                    if ((chosen >> i) & 1u) vlog ^= Minv[i];
                unsigned f = (vlog >> lb) & 15u;
                gp.C[l][g][k] = (unsigned short)(chosen | (f << 12));
            }
        }
    }

    const int smemBytes = NSTATE * sizeof(float4);  // 64 KB dynamic
    static int attrSet = 0;
    if (!attrSet) {
        cudaFuncSetAttribute(qsim_kernel, cudaFuncAttributeMaxDynamicSharedMemorySize, smemBytes);
        attrSet = 1;
    }

    const int grid = (batch + 1) / 2;
    qsim_kernel<<<grid, TPB, smemBytes>>>(x, xN, wts, wN, (float*)d_out,
                                          outFloats, outMode, batch, gp);
}

// round 9
// speedup vs baseline: 1.3399x; 1.3399x over previous
#include <cuda_runtime.h>
#include <cuda_bf16.h>
#include <stdint.h>

// 12-qubit StronglyEntanglingLayers simulator (QDEPTH=8, WIRES=12, reps=1).
//  - normalize/denormalize cancels (circuit is linear) -> skipped
//  - CNOT layers = GF(2)-linear bit maps, host-precomputed, folded into addressing
//  - Rot = RZ(omega) RY(theta) RZ(phi); cross-wire commutation => each layer is
//    Domega * (prod RY_w) * Dphi with 12-wire DIAGONALS. RY pair-update is 8 FMA
//    (vs 16 for full Rot) -> halves mainloop FMA. Diagonals fuse into the
//    group-0 load / group-2 store via bit-linear phase tables (2 sincosf/thread/layer).
//  - conflict-free LDS.64 coset addressing (round-7 host selection)
//  - output: out_size == B*4096 -> real-part float32; == 2*B*4096 -> interleaved.

#define NWIRES 12
#define QD 8
#define NSTATE 4096
#define SMASK (NSTATE - 1)
#define TPB 256

struct GParams {
    unsigned short C[QD][3][8];    // coset basis: low 12 = physical vector, bits 12..15 = flip
    unsigned short CL0[QD][8];     // logical coset basis for group 0 (12 bits)
    unsigned short CL2[QD][8];     // logical coset basis for group 2 (12 bits)
    unsigned short Mm[QD][3][4];   // gate masks (physical images of group logical bits)
    unsigned short Mf[NWIRES];     // final accumulated map (output addressing)
};

__device__ __forceinline__ float2 cmulf(float2 a, float2 b) {
    return make_float2(a.x * b.x - a.y * b.y, a.x * b.y + a.y * b.x);
}

__global__ __launch_bounds__(TPB) void qsim_kernel(
    const float* __restrict__ x, long long xN,
    const float* __restrict__ wts, int wN,
    float* __restrict__ outraw, long long outFloats, int outMode,
    GParams gp)
{
    __shared__ float2 st[NSTATE];           // 32 KB state
    __shared__ float  sUy[QD * NWIRES][2];  // RY (cos, sin) per gate
    __shared__ float  aphi[QD][NWIRES];     // phi angle per layer per logical bit
    __shared__ float  aom[QD][NWIRES];      // omega angle per layer per logical bit
    __shared__ float2 TpC[QD][16];          // phi local-nibble phasors (logical bits 8..11)
    __shared__ float2 ToC[QD][16];          // omega local-nibble phasors (logical bits 0..3)
    __shared__ float  Tpn[QD][2][16];       // phi nonlocal nibble angles (bits 0-3, 4-7)
    __shared__ float  Ton[QD][2][16];       // omega nonlocal nibble angles (bits 4-7, 8-11)

    const int t = threadIdx.x;
    const int s = blockIdx.x;

    // ---- per-gate angles + RY coefficients (one gate per thread, 96 gates) ----
    if (t < QD * NWIRES && t * 3 + 2 < wN) {
        const int l = t / NWIRES, w = t % NWIRES, b = NWIRES - 1 - w;
        float phi = tanhf(wts[t * 3 + 0]);
        float th  = tanhf(wts[t * 3 + 1]);
        float om  = tanhf(wts[t * 3 + 2]);
        float sy, cy;  sincosf(0.5f * th, &sy, &cy);
        sUy[t][0] = cy;  sUy[t][1] = sy;
        aphi[l][b] = phi;
        aom[l][b]  = om;
    }
    __syncthreads();

    // ---- diagonal phase tables (128 threads: l = t>>4, f = t&15) ----
    if (t < 128) {
        const int l = t >> 4, f = t & 15;
        float sp = 0.f, so = 0.f, t0 = 0.f, t1 = 0.f, u0 = 0.f, u1 = 0.f;
        #pragma unroll
        for (int k = 0; k < 4; k++) {
            if ((f >> k) & 1) {
                sp += aphi[l][8 + k];  so += aom[l][k];
                t0 += aphi[l][k];      t1 += aphi[l][4 + k];
                u0 += aom[l][4 + k];   u1 += aom[l][8 + k];
            }
        }
        float Phi = 0.f, Om = 0.f;
        #pragma unroll
        for (int b = 0; b < NWIRES; b++) { Phi += aphi[l][b]; Om += aom[l][b]; }
        float s_, c_;
        sincosf(sp, &s_, &c_);  TpC[l][f] = make_float2(c_, s_);
        sincosf(so, &s_, &c_);  ToC[l][f] = make_float2(c_, s_);
        Tpn[l][0][f] = t0 - 0.5f * Phi;   // fold RZ(phi) global constant
        Tpn[l][1][f] = t1;
        Ton[l][0][f] = u0 - 0.5f * Om;    // fold RZ(omega) global constant
        Ton[l][1][f] = u1;
    }

    // ---- load state (imag = 0); normalization skipped (linear circuit) ----
    {
        const long long xbase = (long long)s * NSTATE;
        #pragma unroll
        for (int j = 0; j < 16; j++) {
            int i = j * TPB + t;
            long long gi = xbase + i;
            float v = (gi < xN) ? x[gi] : 0.0f;
            st[i] = make_float2(v, 0.0f);
        }
    }
    __syncthreads();

    #pragma unroll 1
    for (int l = 0; l < QD; l++) {
        #pragma unroll
        for (int g = 0; g < 3; g++) {
            // thread -> physical coset representative + flip bits
            unsigned acc = 0;
            #pragma unroll
            for (int k = 0; k < 8; k++)
                acc ^= (0u - (((unsigned)t >> k) & 1u)) & (unsigned)gp.C[l][g][k];
            const unsigned pb   = acc & 0xFFFu;
            unsigned flip = acc >> 12;

            const unsigned m0 = gp.Mm[l][g][0], m1 = gp.Mm[l][g][1];
            const unsigned m2 = gp.Mm[l][g][2], m3 = gp.Mm[l][g][3];

            // logical coset base (for diagonal phases; groups 0 and 2 only)
            unsigned Lb = 0;
            if (g != 1) {
                const unsigned short* CL = (g == 0) ? gp.CL0[l] : gp.CL2[l];
                #pragma unroll
                for (int k = 0; k < 8; k++)
                    Lb ^= (0u - (((unsigned)t >> k) & 1u)) & (unsigned)CL[k];
            }

            float2 c[16];
            if (g == 0) {
                // Dphi fused into load: amp *= e^{i anl} * TpC[flip^j]
                const float ap = Tpn[l][0][Lb & 15] + Tpn[l][1][(Lb >> 4) & 15];
                float qs, qc;  sincosf(ap, &qs, &qc);
                const float2 q = make_float2(qc, qs);
                const unsigned fl = Lb >> 8;
                flip = fl;
                #pragma unroll
                for (int j = 0; j < 16; j++) {
                    unsigned a2 = (pb ^ ((j & 1) ? m0 : 0u) ^ ((j & 2) ? m1 : 0u)
                                      ^ ((j & 4) ? m2 : 0u) ^ ((j & 8) ? m3 : 0u)) & SMASK;
                    float2 v = cmulf(st[a2], q);
                    c[j] = cmulf(v, TpC[l][fl ^ j]);
                }
            } else {
                #pragma unroll
                for (int j = 0; j < 16; j++) {
                    unsigned a2 = (pb ^ ((j & 1) ? m0 : 0u) ^ ((j & 2) ? m1 : 0u)
                                      ^ ((j & 4) ? m2 : 0u) ^ ((j & 8) ? m3 : 0u)) & SMASK;
                    c[j] = st[a2];
                }
            }

            // ---- 4 RY gates in registers: slot sl -> wire 4g+3-sl ----
            #pragma unroll
            for (int sl = 0; sl < 4; sl++) {
                const int wire = 4 * g + 3 - sl;
                const float cy = sUy[l * NWIRES + wire][0];
                float sy = sUy[l * NWIRES + wire][1];
                if (flip & (1u << sl)) sy = -sy;   // X RY(th) X = RY(-th)
                #pragma unroll
                for (int j = 0; j < 16; j++) {
                    if (j & (1 << sl)) continue;
                    const int j1 = j | (1 << sl);
                    float2 a  = c[j];
                    float2 b2 = c[j1];
                    c[j]  = make_float2(cy * a.x - sy * b2.x, cy * a.y - sy * b2.y);
                    c[j1] = make_float2(sy * a.x + cy * b2.x, sy * a.y + cy * b2.y);
                }
            }

            if (g == 2) {
                // Domega fused into store
                const float ao = Ton[l][0][(Lb >> 4) & 15] + Ton[l][1][(Lb >> 8) & 15];
                float qs, qc;  sincosf(ao, &qs, &qc);
                const float2 q = make_float2(qc, qs);
                const unsigned fl = Lb & 15;
                #pragma unroll
                for (int j = 0; j < 16; j++) {
                    unsigned a2 = (pb ^ ((j & 1) ? m0 : 0u) ^ ((j & 2) ? m1 : 0u)
                                      ^ ((j & 4) ? m2 : 0u) ^ ((j & 8) ? m3 : 0u)) & SMASK;
                    float2 v = cmulf(c[j], q);
                    st[a2] = cmulf(v, ToC[l][fl ^ j]);
                }
            } else {
                #pragma unroll
                for (int j = 0; j < 16; j++) {
                    unsigned a2 = (pb ^ ((j & 1) ? m0 : 0u) ^ ((j & 2) ? m1 : 0u)
                                      ^ ((j & 4) ? m2 : 0u) ^ ((j & 8) ? m3 : 0u)) & SMASK;
                    st[a2] = c[j];
                }
            }
            __syncthreads();
        }
    }

    // ---- output: logical index j*256+t lives at physical Mf(index) ----
    unsigned mf[NWIRES];
    #pragma unroll
    for (int b = 0; b < NWIRES; b++) mf[b] = gp.Mf[b];

    unsigned Mt = 0;
    #pragma unroll
    for (int k = 0; k < 8; k++)
        Mt ^= (0u - (((unsigned)t >> k) & 1u)) & mf[k];

    const long long obase = (long long)s * NSTATE;
    #pragma unroll
    for (int j = 0; j < 16; j++) {
        unsigned a2 = (Mt ^ ((j & 1) ? mf[8]  : 0u) ^ ((j & 2) ? mf[9]  : 0u)
                          ^ ((j & 4) ? mf[10] : 0u) ^ ((j & 8) ? mf[11] : 0u)) & SMASK;
        long long amp = obase + j * TPB + t;
        float2 v = st[a2];
        if (outMode == 0) {
            if (amp < outFloats) outraw[amp] = v.x;
        } else {
            long long f0 = 2 * amp;
            if (f0 + 1 < outFloats) {
                outraw[f0]     = v.x;
                outraw[f0 + 1] = v.y;
            }
        }
    }
}

// ---------------- host ----------------

static inline unsigned short xor_map(const unsigned short* cols, unsigned v) {
    unsigned acc = 0;
    for (int k = 0; k < NWIRES; k++)
        if ((v >> k) & 1u) acc ^= cols[k];
    return (unsigned short)acc;
}

extern "C" void kernel_launch(void* const* d_in, const int* in_sizes, int n_in,
                              void* d_out, int out_size)
{
    const float* x   = nullptr;
    const float* wts = nullptr;
    long long xN = 0; int wN = 0, batch = 0;
    for (int i = 0; i < n_in; i++) {
        const int sz = in_sizes[i];
        if (sz == QD * NWIRES * 3) {
            wts = (const float*)d_in[i];  wN = sz;
        } else if (sz >= NSTATE && (sz % NSTATE) == 0) {
            x = (const float*)d_in[i];  xN = sz;  batch = sz / NSTATE;
        }
    }
    if (!x || !wts || batch <= 0) return;

    const long long nAmp = (long long)batch * NSTATE;
    int outMode = (out_size == 2LL * nAmp) ? 1 : 0;
    long long outFloats = (long long)out_size;

    // ---- accumulated GF(2) maps per layer ----
    unsigned short Ml[QD + 1][NWIRES];
    {
        unsigned short M[NWIRES];
        for (int b = 0; b < NWIRES; b++) M[b] = (unsigned short)(1u << b);
        for (int l = 0; l < QD; l++) {
            for (int b = 0; b < NWIRES; b++) Ml[l][b] = M[b];
            const int r = (l % (NWIRES - 1)) + 1;
            unsigned short Mn[NWIRES];
            for (int b = 0; b < NWIRES; b++) {
                unsigned i = 1u << b;
                for (int w = NWIRES - 1; w >= 0; w--) {
                    const int bc = NWIRES - 1 - w;
                    const int bt = NWIRES - 1 - ((w + r) % NWIRES);
                    i ^= ((i >> bc) & 1u) << bt;
                }
                Mn[b] = xor_map(M, i);
            }
            for (int b = 0; b < NWIRES; b++) M[b] = Mn[b];
        }
        for (int b = 0; b < NWIRES; b++) Ml[QD][b] = M[b];
    }

    GParams gp;
    for (int b = 0; b < NWIRES; b++) gp.Mf[b] = Ml[QD][b];

    for (int l = 0; l < QD; l++) {
        // inverse of M_l via [A|I] row reduction
        unsigned rows[NWIRES];
        for (int i = 0; i < NWIRES; i++) {
            unsigned rr = 0;
            for (int j = 0; j < NWIRES; j++)
                rr |= ((Ml[l][j] >> i) & 1u) << j;
            rows[i] = rr | (1u << (12 + i));
        }
        for (int col = 0; col < NWIRES; col++) {
            int piv = -1;
            for (int i = col; i < NWIRES; i++)
                if ((rows[i] >> col) & 1u) { piv = i; break; }
            unsigned tmp = rows[col]; rows[col] = rows[piv]; rows[piv] = tmp;
            for (int i = 0; i < NWIRES; i++)
                if (i != col && ((rows[i] >> col) & 1u)) rows[i] ^= rows[col];
        }
        unsigned short Minv[NWIRES];
        for (int b = 0; b < NWIRES; b++) {
            unsigned v = 0;
            for (int i = 0; i < NWIRES; i++)
                v |= ((rows[i] >> (12 + b)) & 1u) << i;
            Minv[b] = (unsigned short)v;
        }

        for (int g = 0; g < 3; g++) {
            const int lb = 8 - 4 * g;
            unsigned short m4[4];
            for (int sl = 0; sl < 4; sl++) {
                m4[sl] = Ml[l][lb + sl];
                gp.Mm[l][g][sl] = m4[sl];
            }

            unsigned led[NWIRES]; for (int i = 0; i < NWIRES; i++) led[i] = 0;
            auto tryAdd12 = [&](unsigned v, unsigned* L) -> bool {
                while (v) {
                    int b = 31 - __builtin_clz(v);
                    if (!L[b]) { L[b] = v; return true; }
                    v ^= L[b];
                }
                return false;
            };
            for (int sl = 0; sl < 4; sl++) tryAdd12(m4[sl], led);

            unsigned led4[4] = {0, 0, 0, 0};
            auto tryAdd4 = [&](unsigned v, unsigned* L) -> bool {
                v &= 15u;
                while (v) {
                    int b = 31 - __builtin_clz(v);
                    if (!L[b]) { L[b] = v; return true; }
                    v ^= L[b];
                }
                return false;
            };

            int dlist[8], nd = 0;
            for (int b = 0; b < NWIRES; b++)
                if (b < lb || b > lb + 3) dlist[nd++] = b;

            for (int k = 0; k < 8; k++) {
                unsigned chosen = 0; int found = 0;
                for (int pass = 0; pass < 2 && !found; pass++) {
                    const int lim = (pass == 0) ? 256 : 4096;
                    for (int u = 1; u < lim && !found; u++) {
                        unsigned cand;
                        if (pass == 0) {
                            cand = 0;
                            for (int i = 0; i < 8; i++)
                                if ((u >> i) & 1) cand ^= Ml[l][dlist[i]];
                        } else {
                            cand = (unsigned)u;
                        }
                        unsigned L12[NWIRES]; for (int i = 0; i < NWIRES; i++) L12[i] = led[i];
                        if (!tryAdd12(cand, L12)) continue;
                        if (k < 4) {
                            unsigned L4[4] = {led4[0], led4[1], led4[2], led4[3]};
                            if (!tryAdd4(cand, L4)) continue;
                            for (int i = 0; i < 4; i++) led4[i] = L4[i];
                        }
                        for (int i = 0; i < NWIRES; i++) led[i] = L12[i];
                        chosen = cand; found = 1;
                    }
                }
                // logical-space generator
                unsigned vlog = 0;
                for (int i = 0; i < NWIRES; i++)
                    if ((chosen >> i) & 1u) vlog ^= Minv[i];
                unsigned f = (vlog >> lb) & 15u;
                gp.C[l][g][k] = (unsigned short)(chosen | (f << 12));
                if (g == 0) gp.CL0[l][k] = (unsigned short)vlog;
                if (g == 2) gp.CL2[l][k] = (unsigned short)vlog;
            }
        }
    }

    qsim_kernel<<<batch, TPB>>>(x, xN, wts, wN, (float*)d_out,
                                outFloats, outMode, gp);
}

// round 10
// speedup vs baseline: 1.3894x; 1.0370x over previous
#include <cuda_runtime.h>
#include <cuda_bf16.h>
#include <stdint.h>

// 12-qubit StronglyEntanglingLayers simulator (QDEPTH=8, WIRES=12, reps=1).
//  - normalize/denormalize cancels (circuit is linear) -> skipped
//  - CNOT layers = GF(2)-linear bit maps, host-precomputed, folded into addressing
//  - Rot = RZ(omega) RY(theta) RZ(phi): layer = Domega * (prod RY) * Dphi.
//    RY pair-update = 8 FMA; diagonals fused into g0 load / g2 store.
//  - ALU-minimized addressing: ONE fused 8-step XOR-select chain per group
//    (physical | flip | logical packed in 32-bit table entries) + GRAY-CODE
//    incremental address generation (15 XOR per 16 addresses).
//  - conflict-free LDS.64 coset addressing (host greedy selection)
//  - output: out_size == B*4096 -> real-part float32; == 2*B*4096 -> interleaved.

#define NWIRES 12
#define QD 8
#define NSTATE 4096
#define TPB 256

struct GParams {
    unsigned int   C2[QD][3][8];   // bits 0-11 physical, 12-15 flip, 16-27 logical
    unsigned short Mm[QD][3][4];   // gate masks (physical images of group logical bits)
    unsigned short Mf[NWIRES];     // final accumulated map (output addressing)
};

__device__ __forceinline__ float2 cmulf(float2 a, float2 b) {
    return make_float2(a.x * b.x - a.y * b.y, a.x * b.y + a.y * b.x);
}

__global__ __launch_bounds__(TPB) void qsim_kernel(
    const float* __restrict__ x, long long xN,
    const float* __restrict__ wts, int wN,
    float* __restrict__ outraw, long long outFloats, int outMode,
    GParams gp)
{
    __shared__ float2 st[NSTATE];           // 32 KB state
    __shared__ float  sUy[QD * NWIRES][2];  // RY (cos, sin) per gate
    __shared__ float  aphi[QD][NWIRES];     // phi angle per layer per logical bit
    __shared__ float  aom[QD][NWIRES];      // omega angle per layer per logical bit
    __shared__ float2 TpC[QD][16];          // phi local-nibble phasors (logical bits 8..11)
    __shared__ float2 ToC[QD][16];          // omega local-nibble phasors (logical bits 0..3)
    __shared__ float  Tpn[QD][2][16];       // phi nonlocal nibble angles (bits 0-3, 4-7)
    __shared__ float  Ton[QD][2][16];       // omega nonlocal nibble angles (bits 4-7, 8-11)

    const int t = threadIdx.x;
    const int s = blockIdx.x;

    // ---- per-gate angles + RY coefficients (one gate per thread, 96 gates) ----
    if (t < QD * NWIRES && t * 3 + 2 < wN) {
        const int l = t / NWIRES, w = t % NWIRES, b = NWIRES - 1 - w;
        float phi = tanhf(wts[t * 3 + 0]);
        float th  = tanhf(wts[t * 3 + 1]);
        float om  = tanhf(wts[t * 3 + 2]);
        float sy, cy;  sincosf(0.5f * th, &sy, &cy);
        sUy[t][0] = cy;  sUy[t][1] = sy;
        aphi[l][b] = phi;
        aom[l][b]  = om;
    }
    __syncthreads();

    // ---- diagonal phase tables (128 threads: l = t>>4, f = t&15) ----
    if (t < 128) {
        const int l = t >> 4, f = t & 15;
        float sp = 0.f, so = 0.f, t0 = 0.f, t1 = 0.f, u0 = 0.f, u1 = 0.f;
        #pragma unroll
        for (int k = 0; k < 4; k++) {
            if ((f >> k) & 1) {
                sp += aphi[l][8 + k];  so += aom[l][k];
                t0 += aphi[l][k];      t1 += aphi[l][4 + k];
                u0 += aom[l][4 + k];   u1 += aom[l][8 + k];
            }
        }
        float Phi = 0.f, Om = 0.f;
        #pragma unroll
        for (int b = 0; b < NWIRES; b++) { Phi += aphi[l][b]; Om += aom[l][b]; }
        float s_, c_;
        sincosf(sp, &s_, &c_);  TpC[l][f] = make_float2(c_, s_);
        sincosf(so, &s_, &c_);  ToC[l][f] = make_float2(c_, s_);
        Tpn[l][0][f] = t0 - 0.5f * Phi;   // fold RZ(phi) global constant
        Tpn[l][1][f] = t1;
        Ton[l][0][f] = u0 - 0.5f * Om;    // fold RZ(omega) global constant
        Ton[l][1][f] = u1;
    }

    // ---- load state (imag = 0); normalization skipped (linear circuit) ----
    {
        const long long xbase = (long long)s * NSTATE;
        #pragma unroll
        for (int j = 0; j < 16; j++) {
            int i = j * TPB + t;
            long long gi = xbase + i;
            float v = (gi < xN) ? x[gi] : 0.0f;
            st[i] = make_float2(v, 0.0f);
        }
    }
    __syncthreads();

    #pragma unroll 1
    for (int l = 0; l < QD; l++) {
        #pragma unroll
        for (int g = 0; g < 3; g++) {
            // fused coset chain: physical base + flip nibble + logical vector
            unsigned acc = 0;
            #pragma unroll
            for (int k = 0; k < 8; k++)
                acc ^= (0u - (((unsigned)t >> k) & 1u)) & gp.C2[l][g][k];
            const unsigned pb   = acc & 0xFFFu;
            const unsigned flip = (acc >> 12) & 15u;
            const unsigned Lb   = acc >> 16;

            unsigned msk[4];
            msk[0] = gp.Mm[l][g][0];  msk[1] = gp.Mm[l][g][1];
            msk[2] = gp.Mm[l][g][2];  msk[3] = gp.Mm[l][g][3];

            // Gray-code visiting order and per-step mask index
            const int GO[16] = {0,1,3,2,6,7,5,4,12,13,15,14,10,11,9,8};
            const int GS[15] = {0,1,0,2,0,1,0,3,0,1,0,2,0,1,0};

            float2 c[16];
            if (g == 0) {
                // Dphi fused into load: amp *= e^{i anl} * TpC[flip^j]
                const float ap = Tpn[l][0][Lb & 15] + Tpn[l][1][(Lb >> 4) & 15];
                float qs, qc;  sincosf(ap, &qs, &qc);
                const float2 q = make_float2(qc, qs);
                unsigned adr = pb;
                c[0] = cmulf(cmulf(st[adr], q), TpC[l][flip]);
                #pragma unroll
                for (int n = 1; n < 16; n++) {
                    adr ^= msk[GS[n - 1]];
                    c[GO[n]] = cmulf(cmulf(st[adr], q), TpC[l][flip ^ GO[n]]);
                }
            } else {
                unsigned adr = pb;
                c[0] = st[adr];
                #pragma unroll
                for (int n = 1; n < 16; n++) {
                    adr ^= msk[GS[n - 1]];
                    c[GO[n]] = st[adr];
                }
            }

            // ---- 4 RY gates in registers: slot sl -> wire 4g+3-sl ----
            #pragma unroll
            for (int sl = 0; sl < 4; sl++) {
                const int wire = 4 * g + 3 - sl;
                const float cy = sUy[l * NWIRES + wire][0];
                float sy = sUy[l * NWIRES + wire][1];
                if (flip & (1u << sl)) sy = -sy;   // X RY(th) X = RY(-th)
                #pragma unroll
                for (int j = 0; j < 16; j++) {
                    if (j & (1 << sl)) continue;
                    const int j1 = j | (1 << sl);
                    float2 a  = c[j];
                    float2 b2 = c[j1];
                    c[j]  = make_float2(cy * a.x - sy * b2.x, cy * a.y - sy * b2.y);
                    c[j1] = make_float2(sy * a.x + cy * b2.x, sy * a.y + cy * b2.y);
                }
            }

            if (g == 2) {
                // Domega fused into store
                const float ao = Ton[l][0][(Lb >> 4) & 15] + Ton[l][1][(Lb >> 8) & 15];
                float qs, qc;  sincosf(ao, &qs, &qc);
                const float2 q = make_float2(qc, qs);
                unsigned adr = pb;
                st[adr] = cmulf(cmulf(c[0], q), ToC[l][flip]);
                #pragma unroll
                for (int n = 1; n < 16; n++) {
                    adr ^= msk[GS[n - 1]];
                    st[adr] = cmulf(cmulf(c[GO[n]], q), ToC[l][flip ^ GO[n]]);
                }
            } else {
                unsigned adr = pb;
                st[adr] = c[0];
                #pragma unroll
                for (int n = 1; n < 16; n++) {
                    adr ^= msk[GS[n - 1]];
                    st[adr] = c[GO[n]];
                }
            }
            __syncthreads();
        }
    }

    // ---- output: logical index j*256+t lives at physical Mf(index) ----
    unsigned mf[NWIRES];
    #pragma unroll
    for (int b = 0; b < NWIRES; b++) mf[b] = gp.Mf[b];

    unsigned Mt = 0;
    #pragma unroll
    for (int k = 0; k < 8; k++)
        Mt ^= (0u - (((unsigned)t >> k) & 1u)) & mf[k];

    const long long obase = (long long)s * NSTATE;
    #pragma unroll
    for (int j = 0; j < 16; j++) {
        unsigned a2 = Mt ^ ((j & 1) ? mf[8]  : 0u) ^ ((j & 2) ? mf[9]  : 0u)
                         ^ ((j & 4) ? mf[10] : 0u) ^ ((j & 8) ? mf[11] : 0u);
        long long amp = obase + j * TPB + t;
        float2 v = st[a2];
        if (outMode == 0) {
            if (amp < outFloats) outraw[amp] = v.x;
        } else {
            long long f0 = 2 * amp;
            if (f0 + 1 < outFloats) {
                outraw[f0]     = v.x;
                outraw[f0 + 1] = v.y;
            }
        }
    }
}

// ---------------- host ----------------

static inline unsigned short xor_map(const unsigned short* cols, unsigned v) {
    unsigned acc = 0;
    for (int k = 0; k < NWIRES; k++)
        if ((v >> k) & 1u) acc ^= cols[k];
    return (unsigned short)acc;
}

extern "C" void kernel_launch(void* const* d_in, const int* in_sizes, int n_in,
                              void* d_out, int out_size)
{
    const float* x   = nullptr;
    const float* wts = nullptr;
    long long xN = 0; int wN = 0, batch = 0;
    for (int i = 0; i < n_in; i++) {
        const int sz = in_sizes[i];
        if (sz == QD * NWIRES * 3) {
            wts = (const float*)d_in[i];  wN = sz;
        } else if (sz >= NSTATE && (sz % NSTATE) == 0) {
            x = (const float*)d_in[i];  xN = sz;  batch = sz / NSTATE;
        }
    }
    if (!x || !wts || batch <= 0) return;

    const long long nAmp = (long long)batch * NSTATE;
    int outMode = (out_size == 2LL * nAmp) ? 1 : 0;
    long long outFloats = (long long)out_size;

    // ---- accumulated GF(2) maps per layer ----
    unsigned short Ml[QD + 1][NWIRES];
    {
        unsigned short M[NWIRES];
        for (int b = 0; b < NWIRES; b++) M[b] = (unsigned short)(1u << b);
        for (int l = 0; l < QD; l++) {
            for (int b = 0; b < NWIRES; b++) Ml[l][b] = M[b];
            const int r = (l % (NWIRES - 1)) + 1;
            unsigned short Mn[NWIRES];
            for (int b = 0; b < NWIRES; b++) {
                unsigned i = 1u << b;
                for (int w = NWIRES - 1; w >= 0; w--) {
                    const int bc = NWIRES - 1 - w;
                    const int bt = NWIRES - 1 - ((w + r) % NWIRES);
                    i ^= ((i >> bc) & 1u) << bt;
                }
                Mn[b] = xor_map(M, i);
            }
            for (int b = 0; b < NWIRES; b++) M[b] = Mn[b];
        }
        for (int b = 0; b < NWIRES; b++) Ml[QD][b] = M[b];
    }

    GParams gp;
    for (int b = 0; b < NWIRES; b++) gp.Mf[b] = Ml[QD][b];

    for (int l = 0; l < QD; l++) {
        // inverse of M_l via [A|I] row reduction
        unsigned rows[NWIRES];
        for (int i = 0; i < NWIRES; i++) {
            unsigned rr = 0;
            for (int j = 0; j < NWIRES; j++)
                rr |= ((Ml[l][j] >> i) & 1u) << j;
            rows[i] = rr | (1u << (12 + i));
        }
        for (int col = 0; col < NWIRES; col++) {
            int piv = -1;
            for (int i = col; i < NWIRES; i++)
                if ((rows[i] >> col) & 1u) { piv = i; break; }
            unsigned tmp = rows[col]; rows[col] = rows[piv]; rows[piv] = tmp;
            for (int i = 0; i < NWIRES; i++)
                if (i != col && ((rows[i] >> col) & 1u)) rows[i] ^= rows[col];
        }
        unsigned short Minv[NWIRES];
        for (int b = 0; b < NWIRES; b++) {
            unsigned v = 0;
            for (int i = 0; i < NWIRES; i++)
                v |= ((rows[i] >> (12 + b)) & 1u) << i;
            Minv[b] = (unsigned short)v;
        }

        for (int g = 0; g < 3; g++) {
            const int lb = 8 - 4 * g;
            unsigned short m4[4];
            for (int sl = 0; sl < 4; sl++) {
                m4[sl] = Ml[l][lb + sl];
                gp.Mm[l][g][sl] = m4[sl];
            }

            unsigned led[NWIRES]; for (int i = 0; i < NWIRES; i++) led[i] = 0;
            auto tryAdd12 = [&](unsigned v, unsigned* L) -> bool {
                while (v) {
                    int b = 31 - __builtin_clz(v);
                    if (!L[b]) { L[b] = v; return true; }
                    v ^= L[b];
                }
                return false;
            };
            for (int sl = 0; sl < 4; sl++) tryAdd12(m4[sl], led);

            unsigned led4[4] = {0, 0, 0, 0};
            auto tryAdd4 = [&](unsigned v, unsigned* L) -> bool {
                v &= 15u;
                while (v) {
                    int b = 31 - __builtin_clz(v);
                    if (!L[b]) { L[b] = v; return true; }
                    v ^= L[b];
                }
                return false;
            };

            int dlist[8], nd = 0;
            for (int b = 0; b < NWIRES; b++)
                if (b < lb || b > lb + 3) dlist[nd++] = b;

            for (int k = 0; k < 8; k++) {
                unsigned chosen = 0; int found = 0;
                for (int pass = 0; pass < 2 && !found; pass++) {
                    const int lim = (pass == 0) ? 256 : 4096;
                    for (int u = 1; u < lim && !found; u++) {
                        unsigned cand;
                        if (pass == 0) {
                            cand = 0;
                            for (int i = 0; i < 8; i++)
                                if ((u >> i) & 1) cand ^= Ml[l][dlist[i]];
                        } else {
                            cand = (unsigned)u;
                        }
                        unsigned L12[NWIRES]; for (int i = 0; i < NWIRES; i++) L12[i] = led[i];
                        if (!tryAdd12(cand, L12)) continue;
                        if (k < 4) {
                            unsigned L4[4] = {led4[0], led4[1], led4[2], led4[3]};
                            if (!tryAdd4(cand, L4)) continue;
                            for (int i = 0; i < 4; i++) led4[i] = L4[i];
                        }
                        for (int i = 0; i < NWIRES; i++) led[i] = L12[i];
                        chosen = cand; found = 1;
                    }
                }
                // logical-space generator + flip nibble
                unsigned vlog = 0;
                for (int i = 0; i < NWIRES; i++)
                    if ((chosen >> i) & 1u) vlog ^= Minv[i];
                unsigned f = (vlog >> lb) & 15u;
                gp.C2[l][g][k] = chosen | (f << 12) | ((unsigned)vlog << 16);
            }
        }
    }

    qsim_kernel<<<batch, TPB>>>(x, xN, wts, wN, (float*)d_out,
                                outFloats, outMode, gp);
}

// round 11
// speedup vs baseline: 1.4603x; 1.0510x over previous
#include <cuda_runtime.h>
#include <cuda_bf16.h>
#include <stdint.h>

// 12-qubit StronglyEntanglingLayers simulator (QDEPTH=8, WIRES=12, reps=1).
//  - normalize/denormalize cancels (circuit is linear) -> skipped
//  - CNOT layers = GF(2)-linear bit maps, host-precomputed, folded into addressing
//  - Rot = RZ(omega) RY(theta) RZ(phi): layer = Domega * (prod RY) * Dphi.
//    RY pair-update = 8 FMA; diagonals fused into g0 load / g2 store.
//  - INIT KERNEL precomputes (per launch): gate tables, 256-entry nonlocal
//    phasor tables (kills mainloop sincosf), per-thread coset chains (kills
//    8-step XOR-select chains). Main kernel is pure FMA + Gray-XOR + LDS.
//  - __launch_bounds__(256,2): 2 CTAs/SM -> overlap barrier/LDS latency.
//  - conflict-free LDS.64 coset addressing (host greedy selection)
//  - output: out_size == B*4096 -> real-part float32; == 2*B*4096 -> interleaved.

#define NWIRES 12
#define QD 8
#define NSTATE 4096
#define TPB 256

struct GParams {
    unsigned int   C2[QD][3][8];   // bits 0-11 physical, 12-15 flip, 16-27 logical
    unsigned short Mm[QD][3][4];   // gate masks (physical images of group logical bits)
    unsigned short Mf[NWIRES];     // final accumulated map (output addressing)
};

// ---- per-launch precomputed tables (written by init_kernel) ----
__device__ unsigned d_coset[QD][3][TPB];     // fused coset chain per (l,g,t)
__device__ float2   d_qphi[QD][256];         // phi nonlocal phasor (logical bits 0..7)
__device__ float2   d_qom [QD][256];         // omega nonlocal phasor (logical bits 4..11)
__device__ float2   d_TpCg[QD][16];          // phi local phasors (logical bits 8..11)
__device__ float2   d_ToCg[QD][16];          // omega local phasors (logical bits 0..3)
__device__ float    d_sUyg[QD * NWIRES][2];  // RY (cos, sin) per gate

__device__ __forceinline__ float2 cmulf(float2 a, float2 b) {
    return make_float2(a.x * b.x - a.y * b.y, a.x * b.y + a.y * b.x);
}

__global__ void init_kernel(const float* __restrict__ wts, int wN, GParams gp)
{
    __shared__ float aphi[NWIRES], aom[NWIRES];
    const int l = blockIdx.x;
    const int t = threadIdx.x;

    if (t < NWIRES) {
        const int gi = l * NWIRES + t;
        float phi = 0.f, th = 0.f, om = 0.f;
        if (gi * 3 + 2 < wN) {
            phi = tanhf(wts[gi * 3 + 0]);
            th  = tanhf(wts[gi * 3 + 1]);
            om  = tanhf(wts[gi * 3 + 2]);
        }
        float sy, cy;  sincosf(0.5f * th, &sy, &cy);
        d_sUyg[gi][0] = cy;  d_sUyg[gi][1] = sy;
        const int b = NWIRES - 1 - t;   // axis w <-> logical bit 11-w
        aphi[b] = phi;  aom[b] = om;
    }
    __syncthreads();

    float Phi = 0.f, Om = 0.f;
    #pragma unroll
    for (int b = 0; b < NWIRES; b++) { Phi += aphi[b]; Om += aom[b]; }

    if (t < 16) {
        float sp = 0.f, so = 0.f;
        #pragma unroll
        for (int k = 0; k < 4; k++)
            if ((t >> k) & 1) { sp += aphi[8 + k]; so += aom[k]; }
        float s_, c_;
        sincosf(sp, &s_, &c_);  d_TpCg[l][t] = make_float2(c_, s_);
        sincosf(so, &s_, &c_);  d_ToCg[l][t] = make_float2(c_, s_);
    }

    // 256-entry nonlocal phasors (global -1/2 phase constants folded in)
    {
        float ap = -0.5f * Phi, ao = -0.5f * Om;
        #pragma unroll
        for (int k = 0; k < 8; k++)
            if ((t >> k) & 1) { ap += aphi[k]; ao += aom[4 + k]; }
        float s_, c_;
        sincosf(ap, &s_, &c_);  d_qphi[l][t] = make_float2(c_, s_);
        sincosf(ao, &s_, &c_);  d_qom[l][t]  = make_float2(c_, s_);
    }

    // fused coset chains
    #pragma unroll
    for (int g = 0; g < 3; g++) {
        unsigned acc = 0;
        #pragma unroll
        for (int k = 0; k < 8; k++)
            acc ^= (0u - (((unsigned)t >> k) & 1u)) & gp.C2[l][g][k];
        d_coset[l][g][t] = acc;
    }
}

__global__ __launch_bounds__(TPB, 2) void qsim_kernel(
    const float* __restrict__ x, long long xN,
    float* __restrict__ outraw, long long outFloats, int outMode,
    GParams gp)
{
    __shared__ float2 st[NSTATE];           // 32 KB state
    __shared__ float  sUy[QD * NWIRES][2];  // RY (cos, sin)
    __shared__ float2 TpC[QD][16];          // phi local phasors
    __shared__ float2 ToC[QD][16];          // omega local phasors

    const int t = threadIdx.x;
    const int s = blockIdx.x;

    // ---- copy small tables global -> shared ----
    if (t < QD * NWIRES) { sUy[t][0] = d_sUyg[t][0]; sUy[t][1] = d_sUyg[t][1]; }
    if (t < 128) {
        const int l = t >> 4, f = t & 15;
        TpC[l][f] = d_TpCg[l][f];
        ToC[l][f] = d_ToCg[l][f];
    }

    // ---- load state (imag = 0); normalization skipped (linear circuit) ----
    {
        const long long xbase = (long long)s * NSTATE;
        #pragma unroll
        for (int j = 0; j < 16; j++) {
            int i = j * TPB + t;
            long long gi = xbase + i;
            float v = (gi < xN) ? x[gi] : 0.0f;
            st[i] = make_float2(v, 0.0f);
        }
    }
    __syncthreads();

    #pragma unroll 1
    for (int l = 0; l < QD; l++) {
        #pragma unroll
        for (int g = 0; g < 3; g++) {
            const unsigned acc  = d_coset[l][g][t];
            const unsigned pb   = acc & 0xFFFu;
            const unsigned flip = (acc >> 12) & 15u;
            const unsigned Lb   = acc >> 16;

            unsigned msk[4];
            msk[0] = gp.Mm[l][g][0];  msk[1] = gp.Mm[l][g][1];
            msk[2] = gp.Mm[l][g][2];  msk[3] = gp.Mm[l][g][3];

            // Gray-code visiting order and per-step mask index
            const int GO[16] = {0,1,3,2,6,7,5,4,12,13,15,14,10,11,9,8};
            const int GS[15] = {0,1,0,2,0,1,0,3,0,1,0,2,0,1,0};

            float2 c[16];
            if (g == 0) {
                // Dphi fused into load: amp *= qphi(nonlocal) * TpC[flip^j]
                const float2 q = d_qphi[l][Lb & 255];
                unsigned adr = pb;
                c[0] = cmulf(cmulf(st[adr], q), TpC[l][flip]);
                #pragma unroll
                for (int n = 1; n < 16; n++) {
                    adr ^= msk[GS[n - 1]];
                    c[GO[n]] = cmulf(cmulf(st[adr], q), TpC[l][flip ^ GO[n]]);
                }
            } else {
                unsigned adr = pb;
                c[0] = st[adr];
                #pragma unroll
                for (int n = 1; n < 16; n++) {
                    adr ^= msk[GS[n - 1]];
                    c[GO[n]] = st[adr];
                }
            }

            // ---- 4 RY gates in registers: slot sl -> wire 4g+3-sl ----
            #pragma unroll
            for (int sl = 0; sl < 4; sl++) {
                const int wire = 4 * g + 3 - sl;
                const float cy = sUy[l * NWIRES + wire][0];
                float sy = sUy[l * NWIRES + wire][1];
                if (flip & (1u << sl)) sy = -sy;   // X RY(th) X = RY(-th)
                #pragma unroll
                for (int j = 0; j < 16; j++) {
                    if (j & (1 << sl)) continue;
                    const int j1 = j | (1 << sl);
                    float2 a  = c[j];
                    float2 b2 = c[j1];
                    c[j]  = make_float2(cy * a.x - sy * b2.x, cy * a.y - sy * b2.y);
                    c[j1] = make_float2(sy * a.x + cy * b2.x, sy * a.y + cy * b2.y);
                }
            }

            if (g == 2) {
                // Domega fused into store
                const float2 q = d_qom[l][(Lb >> 4) & 255];
                unsigned adr = pb;
                st[adr] = cmulf(cmulf(c[0], q), ToC[l][flip]);
                #pragma unroll
                for (int n = 1; n < 16; n++) {
                    adr ^= msk[GS[n - 1]];
                    st[adr] = cmulf(cmulf(c[GO[n]], q), ToC[l][flip ^ GO[n]]);
                }
            } else {
                unsigned adr = pb;
                st[adr] = c[0];
                #pragma unroll
                for (int n = 1; n < 16; n++) {
                    adr ^= msk[GS[n - 1]];
                    st[adr] = c[GO[n]];
                }
            }
            __syncthreads();
        }
    }

    // ---- output: logical index j*256+t lives at physical Mf(index) ----
    unsigned mf[NWIRES];
    #pragma unroll
    for (int b = 0; b < NWIRES; b++) mf[b] = gp.Mf[b];

    unsigned Mt = 0;
    #pragma unroll
    for (int k = 0; k < 8; k++)
        Mt ^= (0u - (((unsigned)t >> k) & 1u)) & mf[k];

    const long long obase = (long long)s * NSTATE;
    #pragma unroll
    for (int j = 0; j < 16; j++) {
        unsigned a2 = Mt ^ ((j & 1) ? mf[8]  : 0u) ^ ((j & 2) ? mf[9]  : 0u)
                         ^ ((j & 4) ? mf[10] : 0u) ^ ((j & 8) ? mf[11] : 0u);
        long long amp = obase + j * TPB + t;
        float2 v = st[a2];
        if (outMode == 0) {
            if (amp < outFloats) outraw[amp] = v.x;
        } else {
            long long f0 = 2 * amp;
            if (f0 + 1 < outFloats) {
                outraw[f0]     = v.x;
                outraw[f0 + 1] = v.y;
            }
        }
    }
}

// ---------------- host ----------------

static inline unsigned short xor_map(const unsigned short* cols, unsigned v) {
    unsigned acc = 0;
    for (int k = 0; k < NWIRES; k++)
        if ((v >> k) & 1u) acc ^= cols[k];
    return (unsigned short)acc;
}

extern "C" void kernel_launch(void* const* d_in, const int* in_sizes, int n_in,
                              void* d_out, int out_size)
{
    const float* x   = nullptr;
    const float* wts = nullptr;
    long long xN = 0; int wN = 0, batch = 0;
    for (int i = 0; i < n_in; i++) {
        const int sz = in_sizes[i];
        if (sz == QD * NWIRES * 3) {
            wts = (const float*)d_in[i];  wN = sz;
        } else if (sz >= NSTATE && (sz % NSTATE) == 0) {
            x = (const float*)d_in[i];  xN = sz;  batch = sz / NSTATE;
        }
    }
    if (!x || !wts || batch <= 0) return;

    const long long nAmp = (long long)batch * NSTATE;
    int outMode = (out_size == 2LL * nAmp) ? 1 : 0;
    long long outFloats = (long long)out_size;

    // ---- accumulated GF(2) maps per layer ----
    unsigned short Ml[QD + 1][NWIRES];
    {
        unsigned short M[NWIRES];
        for (int b = 0; b < NWIRES; b++) M[b] = (unsigned short)(1u << b);
        for (int l = 0; l < QD; l++) {
            for (int b = 0; b < NWIRES; b++) Ml[l][b] = M[b];
            const int r = (l % (NWIRES - 1)) + 1;
            unsigned short Mn[NWIRES];
            for (int b = 0; b < NWIRES; b++) {
                unsigned i = 1u << b;
                for (int w = NWIRES - 1; w >= 0; w--) {
                    const int bc = NWIRES - 1 - w;
                    const int bt = NWIRES - 1 - ((w + r) % NWIRES);
                    i ^= ((i >> bc) & 1u) << bt;
                }
                Mn[b] = xor_map(M, i);
            }
            for (int b = 0; b < NWIRES; b++) M[b] = Mn[b];
        }
        for (int b = 0; b < NWIRES; b++) Ml[QD][b] = M[b];
    }

    GParams gp;
    for (int b = 0; b < NWIRES; b++) gp.Mf[b] = Ml[QD][b];

    for (int l = 0; l < QD; l++) {
        // inverse of M_l via [A|I] row reduction
        unsigned rows[NWIRES];
        for (int i = 0; i < NWIRES; i++) {
            unsigned rr = 0;
            for (int j = 0; j < NWIRES; j++)
                rr |= ((Ml[l][j] >> i) & 1u) << j;
            rows[i] = rr | (1u << (12 + i));
        }
        for (int col = 0; col < NWIRES; col++) {
            int piv = -1;
            for (int i = col; i < NWIRES; i++)
                if ((rows[i] >> col) & 1u) { piv = i; break; }
            unsigned tmp = rows[col]; rows[col] = rows[piv]; rows[piv] = tmp;
            for (int i = 0; i < NWIRES; i++)
                if (i != col && ((rows[i] >> col) & 1u)) rows[i] ^= rows[col];
        }
        unsigned short Minv[NWIRES];
        for (int b = 0; b < NWIRES; b++) {
            unsigned v = 0;
            for (int i = 0; i < NWIRES; i++)
                v |= ((rows[i] >> (12 + b)) & 1u) << i;
            Minv[b] = (unsigned short)v;
        }

        for (int g = 0; g < 3; g++) {
            const int lb = 8 - 4 * g;
            unsigned short m4[4];
            for (int sl = 0; sl < 4; sl++) {
                m4[sl] = Ml[l][lb + sl];
                gp.Mm[l][g][sl] = m4[sl];
            }

            unsigned led[NWIRES]; for (int i = 0; i < NWIRES; i++) led[i] = 0;
            auto tryAdd12 = [&](unsigned v, unsigned* L) -> bool {
                while (v) {
                    int b = 31 - __builtin_clz(v);
                    if (!L[b]) { L[b] = v; return true; }
                    v ^= L[b];
                }
                return false;
            };
            for (int sl = 0; sl < 4; sl++) tryAdd12(m4[sl], led);

            unsigned led4[4] = {0, 0, 0, 0};
            auto tryAdd4 = [&](unsigned v, unsigned* L) -> bool {
                v &= 15u;
                while (v) {
                    int b = 31 - __builtin_clz(v);
                    if (!L[b]) { L[b] = v; return true; }
                    v ^= L[b];
                }
                return false;
            };

            int dlist[8], nd = 0;
            for (int b = 0; b < NWIRES; b++)
                if (b < lb || b > lb + 3) dlist[nd++] = b;

            for (int k = 0; k < 8; k++) {
                unsigned chosen = 0; int found = 0;
                for (int pass = 0; pass < 2 && !found; pass++) {
                    const int lim = (pass == 0) ? 256 : 4096;
                    for (int u = 1; u < lim && !found; u++) {
                        unsigned cand;
                        if (pass == 0) {
                            cand = 0;
                            for (int i = 0; i < 8; i++)
                                if ((u >> i) & 1) cand ^= Ml[l][dlist[i]];
                        } else {
                            cand = (unsigned)u;
                        }
                        unsigned L12[NWIRES]; for (int i = 0; i < NWIRES; i++) L12[i] = led[i];
                        if (!tryAdd12(cand, L12)) continue;
                        if (k < 4) {
                            unsigned L4[4] = {led4[0], led4[1], led4[2], led4[3]};
                            if (!tryAdd4(cand, L4)) continue;
                            for (int i = 0; i < 4; i++) led4[i] = L4[i];
                        }
                        for (int i = 0; i < NWIRES; i++) led[i] = L12[i];
                        chosen = cand; found = 1;
                    }
                }
                // logical-space generator + flip nibble
                unsigned vlog = 0;
                for (int i = 0; i < NWIRES; i++)
                    if ((chosen >> i) & 1u) vlog ^= Minv[i];
                unsigned f = (vlog >> lb) & 15u;
                gp.C2[l][g][k] = chosen | (f << 12) | ((unsigned)vlog << 16);
            }
        }
    }

    init_kernel<<<QD, TPB>>>(wts, wN, gp);
    qsim_kernel<<<batch, TPB>>>(x, xN, (float*)d_out, outFloats, outMode, gp);
}

// round 12
// speedup vs baseline: 1.5794x; 1.0816x over previous
#include <cuda_runtime.h>
#include <cuda_bf16.h>
#include <stdint.h>

// 12-qubit StronglyEntanglingLayers simulator (QDEPTH=8, WIRES=12, reps=1).
//  - normalize/denormalize cancels (circuit is linear) -> skipped
//  - CNOT layers = GF(2)-linear bit maps, host-precomputed, folded into addressing
//  - Rot = RZ(omega) RY(theta) RZ(phi): layer = Domega * (prod RY) * Dphi.
//    RY pair-update = 8 FMA; diagonals fused into g0 load / g2 store.
//  - init kernel precomputes gate tables, 256-entry nonlocal phasors, and
//    per-thread fused coset chains. Main kernel = FMA + Gray-XOR + LDS only.
//  - __launch_bounds__(256,3): cap regs ~84 -> 3 CTAs/SM (24 warps) to cover
//    LDS latency + barrier drains (round-11 profile: latency-bound at 16 warps).
//  - conflict-free LDS.64 coset addressing (host greedy selection)
//  - output: out_size == B*4096 -> real-part float32; == 2*B*4096 -> interleaved.

#define NWIRES 12
#define QD 8
#define NSTATE 4096
#define TPB 256

struct GParams {
    unsigned int   C2[QD][3][8];   // bits 0-11 physical, 12-15 flip, 16-27 logical
    unsigned short Mm[QD][3][4];   // gate masks (physical images of group logical bits)
    unsigned short Mf[NWIRES];     // final accumulated map (output addressing)
};

// ---- per-launch precomputed tables (written by init_kernel) ----
__device__ unsigned d_coset[QD][3][TPB];     // fused coset chain per (l,g,t)
__device__ float2   d_qphi[QD][256];         // phi nonlocal phasor (logical bits 0..7)
__device__ float2   d_qom [QD][256];         // omega nonlocal phasor (logical bits 4..11)
__device__ float2   d_TpCg[QD][16];          // phi local phasors (logical bits 8..11)
__device__ float2   d_ToCg[QD][16];          // omega local phasors (logical bits 0..3)
__device__ float    d_sUyg[QD * NWIRES][2];  // RY (cos, sin) per gate

__device__ __forceinline__ float2 cmulf(float2 a, float2 b) {
    return make_float2(a.x * b.x - a.y * b.y, a.x * b.y + a.y * b.x);
}

__global__ void init_kernel(const float* __restrict__ wts, int wN, GParams gp)
{
    __shared__ float aphi[NWIRES], aom[NWIRES];
    const int l = blockIdx.x;
    const int t = threadIdx.x;

    if (t < NWIRES) {
        const int gi = l * NWIRES + t;
        float phi = 0.f, th = 0.f, om = 0.f;
        if (gi * 3 + 2 < wN) {
            phi = tanhf(wts[gi * 3 + 0]);
            th  = tanhf(wts[gi * 3 + 1]);
            om  = tanhf(wts[gi * 3 + 2]);
        }
        float sy, cy;  sincosf(0.5f * th, &sy, &cy);
        d_sUyg[gi][0] = cy;  d_sUyg[gi][1] = sy;
        const int b = NWIRES - 1 - t;   // axis w <-> logical bit 11-w
        aphi[b] = phi;  aom[b] = om;
    }
    __syncthreads();

    float Phi = 0.f, Om = 0.f;
    #pragma unroll
    for (int b = 0; b < NWIRES; b++) { Phi += aphi[b]; Om += aom[b]; }

    if (t < 16) {
        float sp = 0.f, so = 0.f;
        #pragma unroll
        for (int k = 0; k < 4; k++)
            if ((t >> k) & 1) { sp += aphi[8 + k]; so += aom[k]; }
        float s_, c_;
        sincosf(sp, &s_, &c_);  d_TpCg[l][t] = make_float2(c_, s_);
        sincosf(so, &s_, &c_);  d_ToCg[l][t] = make_float2(c_, s_);
    }

    // 256-entry nonlocal phasors (global -1/2 phase constants folded in)
    {
        float ap = -0.5f * Phi, ao = -0.5f * Om;
        #pragma unroll
        for (int k = 0; k < 8; k++)
            if ((t >> k) & 1) { ap += aphi[k]; ao += aom[4 + k]; }
        float s_, c_;
        sincosf(ap, &s_, &c_);  d_qphi[l][t] = make_float2(c_, s_);
        sincosf(ao, &s_, &c_);  d_qom[l][t]  = make_float2(c_, s_);
    }

    // fused coset chains
    #pragma unroll
    for (int g = 0; g < 3; g++) {
        unsigned acc = 0;
        #pragma unroll
        for (int k = 0; k < 8; k++)
            acc ^= (0u - (((unsigned)t >> k) & 1u)) & gp.C2[l][g][k];
        d_coset[l][g][t] = acc;
    }
}

__global__ __launch_bounds__(TPB, 3) void qsim_kernel(
    const float* __restrict__ x, long long xN,
    float* __restrict__ outraw, long long outFloats, int outMode,
    GParams gp)
{
    __shared__ float2 st[NSTATE];           // 32 KB state
    __shared__ float  sUy[QD * NWIRES][2];  // RY (cos, sin)
    __shared__ float2 TpC[QD][16];          // phi local phasors
    __shared__ float2 ToC[QD][16];          // omega local phasors

    const int t = threadIdx.x;
    const int s = blockIdx.x;

    // ---- copy small tables global -> shared ----
    if (t < QD * NWIRES) { sUy[t][0] = d_sUyg[t][0]; sUy[t][1] = d_sUyg[t][1]; }
    if (t < 128) {
        const int l = t >> 4, f = t & 15;
        TpC[l][f] = d_TpCg[l][f];
        ToC[l][f] = d_ToCg[l][f];
    }

    // ---- load state (imag = 0); normalization skipped (linear circuit) ----
    {
        const long long xbase = (long long)s * NSTATE;
        #pragma unroll
        for (int j = 0; j < 16; j++) {
            int i = j * TPB + t;
            long long gi = xbase + i;
            float v = (gi < xN) ? x[gi] : 0.0f;
            st[i] = make_float2(v, 0.0f);
        }
    }
    __syncthreads();

    #pragma unroll 1
    for (int l = 0; l < QD; l++) {
        #pragma unroll
        for (int g = 0; g < 3; g++) {
            const unsigned acc  = d_coset[l][g][t];
            const unsigned pb   = acc & 0xFFFu;
            const unsigned flip = (acc >> 12) & 15u;
            const unsigned Lb   = acc >> 16;

            unsigned msk[4];
            msk[0] = gp.Mm[l][g][0];  msk[1] = gp.Mm[l][g][1];
            msk[2] = gp.Mm[l][g][2];  msk[3] = gp.Mm[l][g][3];

            // Gray-code visiting order and per-step mask index
            const int GO[16] = {0,1,3,2,6,7,5,4,12,13,15,14,10,11,9,8};
            const int GS[15] = {0,1,0,2,0,1,0,3,0,1,0,2,0,1,0};

            float2 c[16];
            if (g == 0) {
                // Dphi fused into load: amp *= qphi(nonlocal) * TpC[flip^j]
                const float2 q = d_qphi[l][Lb & 255];
                unsigned adr = pb;
                c[0] = cmulf(cmulf(st[adr], q), TpC[l][flip]);
                #pragma unroll
                for (int n = 1; n < 16; n++) {
                    adr ^= msk[GS[n - 1]];
                    c[GO[n]] = cmulf(cmulf(st[adr], q), TpC[l][flip ^ GO[n]]);
                }
            } else {
                unsigned adr = pb;
                c[0] = st[adr];
                #pragma unroll
                for (int n = 1; n < 16; n++) {
                    adr ^= msk[GS[n - 1]];
                    c[GO[n]] = st[adr];
                }
            }

            // ---- 4 RY gates in registers: slot sl -> wire 4g+3-sl ----
            #pragma unroll
            for (int sl = 0; sl < 4; sl++) {
                const int wire = 4 * g + 3 - sl;
                const float cy = sUy[l * NWIRES + wire][0];
                float sy = sUy[l * NWIRES + wire][1];
                if (flip & (1u << sl)) sy = -sy;   // X RY(th) X = RY(-th)
                #pragma unroll
                for (int j = 0; j < 16; j++) {
                    if (j & (1 << sl)) continue;
                    const int j1 = j | (1 << sl);
                    float2 a  = c[j];
                    float2 b2 = c[j1];
                    c[j]  = make_float2(cy * a.x - sy * b2.x, cy * a.y - sy * b2.y);
                    c[j1] = make_float2(sy * a.x + cy * b2.x, sy * a.y + cy * b2.y);
                }
            }

            if (g == 2) {
                // Domega fused into store
                const float2 q = d_qom[l][(Lb >> 4) & 255];
                unsigned adr = pb;
                st[adr] = cmulf(cmulf(c[0], q), ToC[l][flip]);
                #pragma unroll
                for (int n = 1; n < 16; n++) {
                    adr ^= msk[GS[n - 1]];
                    st[adr] = cmulf(cmulf(c[GO[n]], q), ToC[l][flip ^ GO[n]]);
                }
            } else {
                unsigned adr = pb;
                st[adr] = c[0];
                #pragma unroll
                for (int n = 1; n < 16; n++) {
                    adr ^= msk[GS[n - 1]];
                    st[adr] = c[GO[n]];
                }
            }
            __syncthreads();
        }
    }

    // ---- output: logical index j*256+t lives at physical Mf(index) ----
    unsigned mf[NWIRES];
    #pragma unroll
    for (int b = 0; b < NWIRES; b++) mf[b] = gp.Mf[b];

    unsigned Mt = 0;
    #pragma unroll
    for (int k = 0; k < 8; k++)
        Mt ^= (0u - (((unsigned)t >> k) & 1u)) & mf[k];

    const long long obase = (long long)s * NSTATE;
    #pragma unroll
    for (int j = 0; j < 16; j++) {
        unsigned a2 = Mt ^ ((j & 1) ? mf[8]  : 0u) ^ ((j & 2) ? mf[9]  : 0u)
                         ^ ((j & 4) ? mf[10] : 0u) ^ ((j & 8) ? mf[11] : 0u);
        long long amp = obase + j * TPB + t;
        float2 v = st[a2];
        if (outMode == 0) {
            if (amp < outFloats) outraw[amp] = v.x;
        } else {
            long long f0 = 2 * amp;
            if (f0 + 1 < outFloats) {
                outraw[f0]     = v.x;
                outraw[f0 + 1] = v.y;
            }
        }
    }
}

// ---------------- host ----------------

static inline unsigned short xor_map(const unsigned short* cols, unsigned v) {
    unsigned acc = 0;
    for (int k = 0; k < NWIRES; k++)
        if ((v >> k) & 1u) acc ^= cols[k];
    return (unsigned short)acc;
}

extern "C" void kernel_launch(void* const* d_in, const int* in_sizes, int n_in,
                              void* d_out, int out_size)
{
    const float* x   = nullptr;
    const float* wts = nullptr;
    long long xN = 0; int wN = 0, batch = 0;
    for (int i = 0; i < n_in; i++) {
        const int sz = in_sizes[i];
        if (sz == QD * NWIRES * 3) {
            wts = (const float*)d_in[i];  wN = sz;
        } else if (sz >= NSTATE && (sz % NSTATE) == 0) {
            x = (const float*)d_in[i];  xN = sz;  batch = sz / NSTATE;
        }
    }
    if (!x || !wts || batch <= 0) return;

    const long long nAmp = (long long)batch * NSTATE;
    int outMode = (out_size == 2LL * nAmp) ? 1 : 0;
    long long outFloats = (long long)out_size;

    // ---- accumulated GF(2) maps per layer ----
    unsigned short Ml[QD + 1][NWIRES];
    {
        unsigned short M[NWIRES];
        for (int b = 0; b < NWIRES; b++) M[b] = (unsigned short)(1u << b);
        for (int l = 0; l < QD; l++) {
            for (int b = 0; b < NWIRES; b++) Ml[l][b] = M[b];
            const int r = (l % (NWIRES - 1)) + 1;
            unsigned short Mn[NWIRES];
            for (int b = 0; b < NWIRES; b++) {
                unsigned i = 1u << b;
                for (int w = NWIRES - 1; w >= 0; w--) {
                    const int bc = NWIRES - 1 - w;
                    const int bt = NWIRES - 1 - ((w + r) % NWIRES);
                    i ^= ((i >> bc) & 1u) << bt;
                }
                Mn[b] = xor_map(M, i);
            }
            for (int b = 0; b < NWIRES; b++) M[b] = Mn[b];
        }
        for (int b = 0; b < NWIRES; b++) Ml[QD][b] = M[b];
    }

    GParams gp;
    for (int b = 0; b < NWIRES; b++) gp.Mf[b] = Ml[QD][b];

    for (int l = 0; l < QD; l++) {
        // inverse of M_l via [A|I] row reduction
        unsigned rows[NWIRES];
        for (int i = 0; i < NWIRES; i++) {
            unsigned rr = 0;
            for (int j = 0; j < NWIRES; j++)
                rr |= ((Ml[l][j] >> i) & 1u) << j;
            rows[i] = rr | (1u << (12 + i));
        }
        for (int col = 0; col < NWIRES; col++) {
            int piv = -1;
            for (int i = col; i < NWIRES; i++)
                if ((rows[i] >> col) & 1u) { piv = i; break; }
            unsigned tmp = rows[col]; rows[col] = rows[piv]; rows[piv] = tmp;
            for (int i = 0; i < NWIRES; i++)
                if (i != col && ((rows[i] >> col) & 1u)) rows[i] ^= rows[col];
        }
        unsigned short Minv[NWIRES];
        for (int b = 0; b < NWIRES; b++) {
            unsigned v = 0;
            for (int i = 0; i < NWIRES; i++)
                v |= ((rows[i] >> (12 + b)) & 1u) << i;
            Minv[b] = (unsigned short)v;
        }

        for (int g = 0; g < 3; g++) {
            const int lb = 8 - 4 * g;
            unsigned short m4[4];
            for (int sl = 0; sl < 4; sl++) {
                m4[sl] = Ml[l][lb + sl];
                gp.Mm[l][g][sl] = m4[sl];
            }

            unsigned led[NWIRES]; for (int i = 0; i < NWIRES; i++) led[i] = 0;
            auto tryAdd12 = [&](unsigned v, unsigned* L) -> bool {
                while (v) {
                    int b = 31 - __builtin_clz(v);
                    if (!L[b]) { L[b] = v; return true; }
                    v ^= L[b];
                }
                return false;
            };
            for (int sl = 0; sl < 4; sl++) tryAdd12(m4[sl], led);

            unsigned led4[4] = {0, 0, 0, 0};
            auto tryAdd4 = [&](unsigned v, unsigned* L) -> bool {
                v &= 15u;
                while (v) {
                    int b = 31 - __builtin_clz(v);
                    if (!L[b]) { L[b] = v; return true; }
                    v ^= L[b];
                }
                return false;
            };

            int dlist[8], nd = 0;
            for (int b = 0; b < NWIRES; b++)
                if (b < lb || b > lb + 3) dlist[nd++] = b;

            for (int k = 0; k < 8; k++) {
                unsigned chosen = 0; int found = 0;
                for (int pass = 0; pass < 2 && !found; pass++) {
                    const int lim = (pass == 0) ? 256 : 4096;
                    for (int u = 1; u < lim && !found; u++) {
                        unsigned cand;
                        if (pass == 0) {
                            cand = 0;
                            for (int i = 0; i < 8; i++)
                                if ((u >> i) & 1) cand ^= Ml[l][dlist[i]];
                        } else {
                            cand = (unsigned)u;
                        }
                        unsigned L12[NWIRES]; for (int i = 0; i < NWIRES; i++) L12[i] = led[i];
                        if (!tryAdd12(cand, L12)) continue;
                        if (k < 4) {
                            unsigned L4[4] = {led4[0], led4[1], led4[2], led4[3]};
                            if (!tryAdd4(cand, L4)) continue;
                            for (int i = 0; i < 4; i++) led4[i] = L4[i];
                        }
                        for (int i = 0; i < NWIRES; i++) led[i] = L12[i];
                        chosen = cand; found = 1;
                    }
                }
                // logical-space generator + flip nibble
                unsigned vlog = 0;
                for (int i = 0; i < NWIRES; i++)
                    if ((chosen >> i) & 1u) vlog ^= Minv[i];
                unsigned f = (vlog >> lb) & 15u;
                gp.C2[l][g][k] = chosen | (f << 12) | ((unsigned)vlog << 16);
            }
        }
    }

    init_kernel<<<QD, TPB>>>(wts, wN, gp);
    qsim_kernel<<<batch, TPB>>>(x, xN, (float*)d_out, outFloats, outMode, gp);
}

// round 15
// speedup vs baseline: 1.6418x; 1.0395x over previous
#include <cuda_runtime.h>
#include <cuda_bf16.h>
#include <stdint.h>

// 12-qubit StronglyEntanglingLayers simulator (QDEPTH=8, WIRES=12, reps=1).
//  - normalize/denormalize cancels (circuit is linear) -> skipped
//  - CNOT layers = GF(2)-linear bit maps, folded into addressing
//  - Rot = RZ(omega) RY(theta) RZ(phi): layer = Domega * (prod RY) * Dphi,
//    Dphi fused into g0 load, Domega fused into g2 store (both bit-linear in
//    the layer's own logical basis; NOTE cross-layer diagonal merging through
//    the CNOT permutation is INVALID -- parities are not bit-linear phases).
//  - RY pair-update = rotation by alpha = theta/2, applied via 3-shear lifting
//    (t = tan(theta/4), s = sin(theta/2)): 6 FMA/pair instead of 8.
//  - init kernel precomputes gate tables, 256-entry nonlocal phasors, and
//    per-thread fused coset chains. Main kernel = FMA + Gray-XOR + LDS only.
//  - __launch_bounds__(256,3); conflict-free LDS.64 coset addressing.
//  - output: out_size == B*4096 -> real-part float32; == 2*B*4096 -> interleaved.

#define NWIRES 12
#define QD 8
#define NSTATE 4096
#define TPB 256

struct GParams {
    unsigned int   C2[QD][3][8];   // bits 0-11 physical, 12-15 flip, 16-27 logical
    unsigned short Mm[QD][3][4];   // gate masks (physical images of group logical bits)
    unsigned short Mf[NWIRES];     // final accumulated map (output addressing)
};

// ---- per-launch precomputed tables (written by init_kernel) ----
__device__ unsigned d_coset[QD][3][TPB];     // fused coset chain per (l,g,t)
__device__ float2   d_qphi[QD][256];         // phi nonlocal phasor (logical bits 0..7)
__device__ float2   d_qom [QD][256];         // omega nonlocal phasor (logical bits 4..11)
__device__ float2   d_TpCg[QD][16];          // phi local phasors (logical bits 8..11)
__device__ float2   d_ToCg[QD][16];          // omega local phasors (logical bits 0..3)
__device__ float    d_sUyg[QD * NWIRES][2];  // RY lifting coeffs (tan(th/4), sin(th/2))

__device__ __forceinline__ float2 cmulf(float2 a, float2 b) {
    return make_float2(a.x * b.x - a.y * b.y, a.x * b.y + a.y * b.x);
}

__global__ void init_kernel(const float* __restrict__ wts, int wN, GParams gp)
{
    __shared__ float aphi[NWIRES], aom[NWIRES];
    const int l = blockIdx.x;
    const int t = threadIdx.x;

    if (t < NWIRES) {
        const int gi = l * NWIRES + t;
        float phi = 0.f, th = 0.f, om = 0.f;
        if (gi * 3 + 2 < wN) {
            phi = tanhf(wts[gi * 3 + 0]);
            th  = tanhf(wts[gi * 3 + 1]);
            om  = tanhf(wts[gi * 3 + 2]);
        }
        // pair rotation angle alpha = th/2; lifting uses tan(alpha/2), sin(alpha)
        d_sUyg[gi][0] = tanf(0.25f * th);
        d_sUyg[gi][1] = sinf(0.5f  * th);
        const int b = NWIRES - 1 - t;   // axis w <-> logical bit 11-w
        aphi[b] = phi;  aom[b] = om;
    }
    __syncthreads();

    float Phi = 0.f, Om = 0.f;
    #pragma unroll
    for (int b = 0; b < NWIRES; b++) { Phi += aphi[b]; Om += aom[b]; }

    if (t < 16) {
        float sp = 0.f, so = 0.f;
        #pragma unroll
        for (int k = 0; k < 4; k++)
            if ((t >> k) & 1) { sp += aphi[8 + k]; so += aom[k]; }
        float s_, c_;
        sincosf(sp, &s_, &c_);  d_TpCg[l][t] = make_float2(c_, s_);
        sincosf(so, &s_, &c_);  d_ToCg[l][t] = make_float2(c_, s_);
    }

    // 256-entry nonlocal phasors (global -1/2 phase constants folded in)
    {
        float ap = -0.5f * Phi, ao = -0.5f * Om;
        #pragma unroll
        for (int k = 0; k < 8; k++)
            if ((t >> k) & 1) { ap += aphi[k]; ao += aom[4 + k]; }
        float s_, c_;
        sincosf(ap, &s_, &c_);  d_qphi[l][t] = make_float2(c_, s_);
        sincosf(ao, &s_, &c_);  d_qom[l][t]  = make_float2(c_, s_);
    }

    // fused coset chains
    #pragma unroll
    for (int g = 0; g < 3; g++) {
        unsigned acc = 0;
        #pragma unroll
        for (int k = 0; k < 8; k++)
            acc ^= (0u - (((unsigned)t >> k) & 1u)) & gp.C2[l][g][k];
        d_coset[l][g][t] = acc;
    }
}

__global__ __launch_bounds__(TPB, 3) void qsim_kernel(
    const float* __restrict__ x, long long xN,
    float* __restrict__ outraw, long long outFloats, int outMode,
    GParams gp)
{
    __shared__ float2 st[NSTATE];           // 32 KB state
    __shared__ float  sUy[QD * NWIRES][2];  // RY lifting coeffs
    __shared__ float2 TpC[QD][16];          // phi local phasors
    __shared__ float2 ToC[QD][16];          // omega local phasors

    const int t = threadIdx.x;
    const int s = blockIdx.x;

    // ---- copy small tables global -> shared ----
    if (t < QD * NWIRES) { sUy[t][0] = d_sUyg[t][0]; sUy[t][1] = d_sUyg[t][1]; }
    if (t < 128) {
        const int l = t >> 4, f = t & 15;
        TpC[l][f] = d_TpCg[l][f];
        ToC[l][f] = d_ToCg[l][f];
    }

    // ---- load state (imag = 0); normalization skipped (linear circuit) ----
    {
        const long long xbase = (long long)s * NSTATE;
        #pragma unroll
        for (int j = 0; j < 16; j++) {
            int i = j * TPB + t;
            long long gi = xbase + i;
            float v = (gi < xN) ? x[gi] : 0.0f;
            st[i] = make_float2(v, 0.0f);
        }
    }
    __syncthreads();

    #pragma unroll 1
    for (int l = 0; l < QD; l++) {
        #pragma unroll
        for (int g = 0; g < 3; g++) {
            const unsigned acc  = d_coset[l][g][t];
            const unsigned pb   = acc & 0xFFFu;
            const unsigned flip = (acc >> 12) & 15u;
            const unsigned Lb   = acc >> 16;

            unsigned msk[4];
            msk[0] = gp.Mm[l][g][0];  msk[1] = gp.Mm[l][g][1];
            msk[2] = gp.Mm[l][g][2];  msk[3] = gp.Mm[l][g][3];

            // Gray-code visiting order and per-step mask index
            const int GO[16] = {0,1,3,2,6,7,5,4,12,13,15,14,10,11,9,8};
            const int GS[15] = {0,1,0,2,0,1,0,3,0,1,0,2,0,1,0};

            float2 c[16];
            if (g == 0) {
                // Dphi fused into load: amp *= qphi(nonlocal) * TpC[flip^j]
                const float2 q = d_qphi[l][Lb & 255];
                unsigned adr = pb;
                c[0] = cmulf(cmulf(st[adr], q), TpC[l][flip]);
                #pragma unroll
                for (int n = 1; n < 16; n++) {
                    adr ^= msk[GS[n - 1]];
                    c[GO[n]] = cmulf(cmulf(st[adr], q), TpC[l][flip ^ GO[n]]);
                }
            } else {
                unsigned adr = pb;
                c[0] = st[adr];
                #pragma unroll
                for (int n = 1; n < 16; n++) {
                    adr ^= msk[GS[n - 1]];
                    c[GO[n]] = st[adr];
                }
            }

            // ---- 4 RY gates (lifting: a-=t*b; b+=s*a; a-=t*b) ----
            #pragma unroll
            for (int sl = 0; sl < 4; sl++) {
                const int wire = 4 * g + 3 - sl;
                float tt = sUy[l * NWIRES + wire][0];
                float ss = sUy[l * NWIRES + wire][1];
                if (flip & (1u << sl)) { tt = -tt; ss = -ss; }   // RY(-th)
                #pragma unroll
                for (int j = 0; j < 16; j++) {
                    if (j & (1 << sl)) continue;
                    const int j1 = j | (1 << sl);
                    float2 a  = c[j];
                    float2 b2 = c[j1];
                    a.x  = fmaf(-tt, b2.x, a.x);   a.y  = fmaf(-tt, b2.y, a.y);
                    b2.x = fmaf( ss, a.x,  b2.x);  b2.y = fmaf( ss, a.y,  b2.y);
                    a.x  = fmaf(-tt, b2.x, a.x);   a.y  = fmaf(-tt, b2.y, a.y);
                    c[j]  = a;
                    c[j1] = b2;
                }
            }

            if (g == 2) {
                // Domega fused into store
                const float2 q = d_qom[l][(Lb >> 4) & 255];
                unsigned adr = pb;
                st[adr] = cmulf(cmulf(c[0], q), ToC[l][flip]);
                #pragma unroll
                for (int n = 1; n < 16; n++) {
                    adr ^= msk[GS[n - 1]];
                    st[adr] = cmulf(cmulf(c[GO[n]], q), ToC[l][flip ^ GO[n]]);
                }
            } else {
                unsigned adr = pb;
                st[adr] = c[0];
                #pragma unroll
                for (int n = 1; n < 16; n++) {
                    adr ^= msk[GS[n - 1]];
                    st[adr] = c[GO[n]];
                }
            }
            __syncthreads();
        }
    }

    // ---- output: logical index j*256+t lives at physical Mf(index) ----
    unsigned mf[NWIRES];
    #pragma unroll
    for (int b = 0; b < NWIRES; b++) mf[b] = gp.Mf[b];

    unsigned Mt = 0;
    #pragma unroll
    for (int k = 0; k < 8; k++)
        Mt ^= (0u - (((unsigned)t >> k) & 1u)) & mf[k];

    const long long obase = (long long)s * NSTATE;
    #pragma unroll
    for (int j = 0; j < 16; j++) {
        unsigned a2 = Mt ^ ((j & 1) ? mf[8]  : 0u) ^ ((j & 2) ? mf[9]  : 0u)
                         ^ ((j & 4) ? mf[10] : 0u) ^ ((j & 8) ? mf[11] : 0u);
        long long amp = obase + j * TPB + t;
        float2 v = st[a2];
        if (outMode == 0) {
            if (amp < outFloats) outraw[amp] = v.x;
        } else {
            long long f0 = 2 * amp;
            if (f0 + 1 < outFloats) {
                outraw[f0]     = v.x;
                outraw[f0 + 1] = v.y;
            }
        }
    }
}

// ---------------- host ----------------

static inline unsigned short xor_map(const unsigned short* cols, unsigned v) {
    unsigned acc = 0;
    for (int k = 0; k < NWIRES; k++)
        if ((v >> k) & 1u) acc ^= cols[k];
    return (unsigned short)acc;
}

extern "C" void kernel_launch(void* const* d_in, const int* in_sizes, int n_in,
                              void* d_out, int out_size)
{
    const float* x   = nullptr;
    const float* wts = nullptr;
    long long xN = 0; int wN = 0, batch = 0;
    for (int i = 0; i < n_in; i++) {
        const int sz = in_sizes[i];
        if (sz == QD * NWIRES * 3) {
            wts = (const float*)d_in[i];  wN = sz;
        } else if (sz >= NSTATE && (sz % NSTATE) == 0) {
            x = (const float*)d_in[i];  xN = sz;  batch = sz / NSTATE;
        }
    }
    if (!x || !wts || batch <= 0) return;

    const long long nAmp = (long long)batch * NSTATE;
    int outMode = (out_size == 2LL * nAmp) ? 1 : 0;
    long long outFloats = (long long)out_size;

    // ---- accumulated GF(2) maps per layer ----
    unsigned short Ml[QD + 1][NWIRES];
    {
        unsigned short M[NWIRES];
        for (int b = 0; b < NWIRES; b++) M[b] = (unsigned short)(1u << b);
        for (int l = 0; l < QD; l++) {
            for (int b = 0; b < NWIRES; b++) Ml[l][b] = M[b];
            const int r = (l % (NWIRES - 1)) + 1;
            unsigned short Mn[NWIRES];
            for (int b = 0; b < NWIRES; b++) {
                unsigned i = 1u << b;
                for (int w = NWIRES - 1; w >= 0; w--) {
                    const int bc = NWIRES - 1 - w;
                    const int bt = NWIRES - 1 - ((w + r) % NWIRES);
                    i ^= ((i >> bc) & 1u) << bt;
                }
                Mn[b] = xor_map(M, i);
            }
            for (int b = 0; b < NWIRES; b++) M[b] = Mn[b];
        }
        for (int b = 0; b < NWIRES; b++) Ml[QD][b] = M[b];
    }

    GParams gp;
    for (int b = 0; b < NWIRES; b++) gp.Mf[b] = Ml[QD][b];

    for (int l = 0; l < QD; l++) {
        // inverse of M_l via [A|I] row reduction
        unsigned rows[NWIRES];
        for (int i = 0; i < NWIRES; i++) {
            unsigned rr = 0;
            for (int j = 0; j < NWIRES; j++)
                rr |= ((Ml[l][j] >> i) & 1u) << j;
            rows[i] = rr | (1u << (12 + i));
        }
        for (int col = 0; col < NWIRES; col++) {
            int piv = -1;
            for (int i = col; i < NWIRES; i++)
                if ((rows[i] >> col) & 1u) { piv = i; break; }
            unsigned tmp = rows[col]; rows[col] = rows[piv]; rows[piv] = tmp;
            for (int i = 0; i < NWIRES; i++)
                if (i != col && ((rows[i] >> col) & 1u)) rows[i] ^= rows[col];
        }
        unsigned short Minv[NWIRES];
        for (int b = 0; b < NWIRES; b++) {
            unsigned v = 0;
            for (int i = 0; i < NWIRES; i++)
                v |= ((rows[i] >> (12 + b)) & 1u) << i;
            Minv[b] = (unsigned short)v;
        }

        for (int g = 0; g < 3; g++) {
            const int lb = 8 - 4 * g;
            unsigned short m4[4];
            for (int sl = 0; sl < 4; sl++) {
                m4[sl] = Ml[l][lb + sl];
                gp.Mm[l][g][sl] = m4[sl];
            }

            unsigned led[NWIRES]; for (int i = 0; i < NWIRES; i++) led[i] = 0;
            auto tryAdd12 = [&](unsigned v, unsigned* L) -> bool {
                while (v) {
                    int b = 31 - __builtin_clz(v);
                    if (!L[b]) { L[b] = v; return true; }
                    v ^= L[b];
                }
                return false;
            };
            for (int sl = 0; sl < 4; sl++) tryAdd12(m4[sl], led);

            unsigned led4[4] = {0, 0, 0, 0};
            auto tryAdd4 = [&](unsigned v, unsigned* L) -> bool {
                v &= 15u;
                while (v) {
                    int b = 31 - __builtin_clz(v);
                    if (!L[b]) { L[b] = v; return true; }
                    v ^= L[b];
                }
                return false;
            };

            int dlist[8], nd = 0;
            for (int b = 0; b < NWIRES; b++)
                if (b < lb || b > lb + 3) dlist[nd++] = b;

            for (int k = 0; k < 8; k++) {
                unsigned chosen = 0; int found = 0;
                for (int pass = 0; pass < 2 && !found; pass++) {
                    const int lim = (pass == 0) ? 256 : 4096;
                    for (int u = 1; u < lim && !found; u++) {
                        unsigned cand;
                        if (pass == 0) {
                            cand = 0;
                            for (int i = 0; i < 8; i++)
                                if ((u >> i) & 1) cand ^= Ml[l][dlist[i]];
                        } else {
                            cand = (unsigned)u;
                        }
                        unsigned L12[NWIRES]; for (int i = 0; i < NWIRES; i++) L12[i] = led[i];
                        if (!tryAdd12(cand, L12)) continue;
                        if (k < 4) {
                            unsigned L4[4] = {led4[0], led4[1], led4[2], led4[3]};
                            if (!tryAdd4(cand, L4)) continue;
                            for (int i = 0; i < 4; i++) led4[i] = L4[i];
                        }
                        for (int i = 0; i < NWIRES; i++) led[i] = L12[i];
                        chosen = cand; found = 1;
                    }
                }
                // logical-space generator + flip nibble
                unsigned vlog = 0;
                for (int i = 0; i < NWIRES; i++)
                    if ((chosen >> i) & 1u) vlog ^= Minv[i];
                unsigned f = (vlog >> lb) & 15u;
                gp.C2[l][g][k] = chosen | (f << 12) | ((unsigned)vlog << 16);
            }
        }
    }

    init_kernel<<<QD, TPB>>>(wts, wN, gp);
    qsim_kernel<<<batch, TPB>>>(x, xN, (float*)d_out, outFloats, outMode, gp);
}